// round 13
// baseline (speedup 1.0000x reference)
#include <cuda_runtime.h>
#include <cuda_bf16.h>
#include <cuda_fp16.h>
#include <math.h>
#include <stdint.h>

// Problem constants
#define NFEAT   256
#define NHID    128
#define NCLASS  40
#define MAXN    100000
#define MAXE    3200000
#define ELLW    96            // ELL width: P(Poisson(32) > 96) ~ 1e-20
#define NPAD    (MAXN + 128)  // rows padded so cp.async tail reads stay in-bounds

// ---------------------------------------------------------------------------
// Static device scratch
// ---------------------------------------------------------------------------
__device__ int    g_cnt[MAXN];                     // degree (atomic slot counter)
__device__ int    g_ell[(size_t)MAXN * ELLW];      // ELL adjacency (38.4 MB)
__device__ float  g_s[(size_t)MAXN * NHID];        // self-projection (fp32)
__device__ __half g_z[(size_t)MAXN * NHID];        // neigh-projection (fp16)
__device__ uint8_t g_z8[(size_t)MAXN * NHID];      // quantized z, BIASED bytes (q+128)
__device__ float  g_zsc[MAXN];                     // per-row z scale
__device__ __half g_h1[(size_t)NPAD * NHID];       // h1 (fp16, GEMM2 A operand)
// fp16 weights, [128 out-rows, K in-cols] K-major (= torch native slices)
__device__ __half g_w1s[128 * 256], g_w1n[128 * 256];
__device__ __half g_w2s[128 * 128], g_w2n[128 * 128];

// ---------------------------------------------------------------------------
// Helpers
// ---------------------------------------------------------------------------
__device__ __forceinline__ uint32_t smem_u32(const void* p) {
    uint32_t a;
    asm("{ .reg .u64 t; cvta.to.shared.u64 t, %1; cvt.u32.u64 %0, t; }"
        : "=r"(a) : "l"(p));
    return a;
}

#define SWZ(x) ((x) ^ (((x) >> 3) & 0x70))

__device__ __forceinline__ void ldsm_x4(uint32_t addr, uint32_t& r0, uint32_t& r1,
                                        uint32_t& r2, uint32_t& r3) {
    asm volatile("ldmatrix.sync.aligned.m8n8.x4.shared.b16 {%0,%1,%2,%3}, [%4];"
                 : "=r"(r0), "=r"(r1), "=r"(r2), "=r"(r3) : "r"(addr));
}

__device__ __forceinline__ void mma_fp16(float* d, const uint32_t* a,
                                         uint32_t b0, uint32_t b1) {
    asm volatile(
        "mma.sync.aligned.m16n8k16.row.col.f32.f16.f16.f32 "
        "{%0,%1,%2,%3}, {%4,%5,%6,%7}, {%8,%9}, {%0,%1,%2,%3};"
        : "+f"(d[0]), "+f"(d[1]), "+f"(d[2]), "+f"(d[3])
        : "r"(a[0]), "r"(a[1]), "r"(a[2]), "r"(a[3]), "r"(b0), "r"(b1));
}

__device__ __forceinline__ void cp16(uint32_t dst, const void* src) {
    asm volatile("cp.async.cg.shared.global [%0], [%1], 16;"
                 :: "r"(dst), "l"(src));
}
#define CP_COMMIT() asm volatile("cp.async.commit_group;" ::: "memory")
#define CP_WAIT0()  asm volatile("cp.async.wait_group 0;" ::: "memory")

// ---------------------------------------------------------------------------
// Merged prep: W1 -> fp16 slices (idx<32768), W2 (idx<16384), zero g_cnt
// ---------------------------------------------------------------------------
__global__ void prep_kernel(const float* __restrict__ W1,
                            const float* __restrict__ W2, int n) {
    int idx = blockIdx.x * blockDim.x + threadIdx.x;
    if (idx < 128 * 256) {
        int j = idx >> 8, k = idx & 255;
        g_w1s[idx] = __float2half_rn(W1[j * 512 + k]);
        g_w1n[idx] = __float2half_rn(W1[j * 512 + 256 + k]);
    }
    if (idx < 128 * 128) {
        int j = idx >> 7, k = idx & 127;
        g_w2s[idx] = __float2half_rn(W2[j * 256 + k]);
        g_w2n[idx] = __float2half_rn(W2[j * 256 + 128 + k]);
    }
    if (idx < n) g_cnt[idx] = 0;
}

// ---------------------------------------------------------------------------
// Merged double-buffered fp16 GEMM (mma.sync m16n8k16) — R10-proven epilogue:
//   s[blk,128] = A @ Bs^T (fp32 out),  z[blk,128] = A @ Bn^T (fp16 out)
// Block 128 rows x 256 out-cols, 512 threads = 16 warps (4 M x 4 N of 32x64).
// AFP32: A fp32 in gmem, converted to fp16 in smem (register-prefetched).
// EFILL: blocks with blockIdx.x >= gemm_blocks build the ELL adjacency.
// ---------------------------------------------------------------------------
template <int K, bool AFP32, bool EFILL>
__global__ __launch_bounds__(512, 1) void mma_gemm_kernel(
    const float* __restrict__ A,
    const __half* __restrict__ Ah,
    const __half* __restrict__ Bs, const __half* __restrict__ Bn,
    float* __restrict__ Cs, __half* __restrict__ Cz, int n,
    int gemm_blocks, const int* __restrict__ rows,
    const int* __restrict__ cols, int e) {
    // ---- ELL-fill role (tail blocks) ----
    if (EFILL && (int)blockIdx.x >= gemm_blocks) {
        const int fb  = blockIdx.x - gemm_blocks;
        const int nfb = gridDim.x - gemm_blocks;
        const int tid = threadIdx.x;
        const int total4 = e >> 2;
        const int4* r4p = (const int4*)rows;
        const int4* c4p = (const int4*)cols;
        for (int i = fb * 512 + tid; i < total4; i += nfb * 512) {
            int4 r = __ldg(&r4p[i]);
            int4 c = __ldg(&c4p[i]);
            int p;
            p = atomicAdd(&g_cnt[r.x], 1); if (p < ELLW) g_ell[(size_t)r.x * ELLW + p] = c.x;
            p = atomicAdd(&g_cnt[r.y], 1); if (p < ELLW) g_ell[(size_t)r.y * ELLW + p] = c.y;
            p = atomicAdd(&g_cnt[r.z], 1); if (p < ELLW) g_ell[(size_t)r.z * ELLW + p] = c.z;
            p = atomicAdd(&g_cnt[r.w], 1); if (p < ELLW) g_ell[(size_t)r.w * ELLW + p] = c.w;
        }
        if (fb == 0) {       // scalar tail (e % 4)
            for (int i = (total4 << 2) + tid; i < e; i += 512) {
                int r = __ldg(&rows[i]), c = __ldg(&cols[i]);
                int p = atomicAdd(&g_cnt[r], 1);
                if (p < ELLW) g_ell[(size_t)r * ELLW + p] = c;
            }
        }
        return;
    }

    extern __shared__ char smem[];
    constexpr int BUF  = 49152;          // A 16K + Bs 16K + Bn 16K
    constexpr int AOFF = 0;
    constexpr int BOFF = 16384;
    constexpr int NC   = K / 64;
    const uint32_t sb = smem_u32(smem);
    const int tid    = threadIdx.x;
    const int lane   = tid & 31;
    const int wid    = tid >> 5;
    const int warp_m = wid & 3;
    const int warp_n = wid >> 2;
    const int row0   = blockIdx.x * 128;

    float acc[2][8][4];
    #pragma unroll
    for (int m = 0; m < 2; ++m)
        #pragma unroll
        for (int f = 0; f < 8; ++f)
            #pragma unroll
            for (int q = 0; q < 4; ++q) acc[m][f][q] = 0.f;

    auto stage_B = [&](int c, int buf) {
        #pragma unroll
        for (int t = 0; t < 2; ++t) {
            const __half* B = t ? Bn : Bs;
            #pragma unroll
            for (int i = tid; i < 1024; i += 512) {
                int row = i >> 3, j = i & 7;
                cp16(sb + buf * BUF + BOFF + t * 16384 + SWZ((uint32_t)(row * 128 + j * 16)),
                     B + (size_t)row * K + c * 64 + j * 8);
            }
        }
    };
    auto stage_A_async = [&](int c, int buf) {
        #pragma unroll
        for (int i = tid; i < 1024; i += 512) {
            int row = i >> 3, j = i & 7;
            cp16(sb + buf * BUF + AOFF + SWZ((uint32_t)(row * 128 + j * 16)),
                 Ah + (size_t)(row0 + row) * K + c * 64 + j * 8);
        }
    };
    float ar[2][8];
    auto load_A_regs = [&](int c) {
        #pragma unroll
        for (int t = 0; t < 2; ++t) {
            int g = tid + t * 512;
            int row = g >> 3, j = g & 7;
            int grow = row0 + row;
            float4 f0 = make_float4(0.f, 0.f, 0.f, 0.f), f1 = f0;
            if (grow < n) {
                const float* ap = A + (size_t)grow * K + c * 64 + j * 8;
                f0 = *(const float4*)ap;
                f1 = *(const float4*)(ap + 4);
            }
            ar[t][0] = f0.x; ar[t][1] = f0.y; ar[t][2] = f0.z; ar[t][3] = f0.w;
            ar[t][4] = f1.x; ar[t][5] = f1.y; ar[t][6] = f1.z; ar[t][7] = f1.w;
        }
    };
    auto convert_store_A = [&](int buf) {
        #pragma unroll
        for (int t = 0; t < 2; ++t) {
            int g = tid + t * 512;
            int row = g >> 3, j = g & 7;
            uint32_t hv[4];
            #pragma unroll
            for (int q = 0; q < 4; ++q) {
                __half2 hp = __floats2half2_rn(ar[t][2 * q], ar[t][2 * q + 1]);
                hv[q] = *reinterpret_cast<uint32_t*>(&hp);
            }
            *(uint4*)(smem + buf * BUF + AOFF + SWZ((uint32_t)(row * 128 + j * 16))) =
                make_uint4(hv[0], hv[1], hv[2], hv[3]);
        }
    };

    const uint32_t b_tile = BOFF + (warp_n >> 1) * 16384;   // Bs or Bn tile
    const int b_row_base = (warp_n & 1) * 64 + ((lane >> 4) << 3) + (lane & 7);
    const uint32_t b_colb = ((lane >> 3) & 1) * 16;

    stage_B(0, 0);
    if (!AFP32) {
        stage_A_async(0, 0);
        CP_COMMIT();
    } else {
        CP_COMMIT();
        load_A_regs(0);
        convert_store_A(0);
    }
    CP_WAIT0();
    __syncthreads();

    for (int c = 0; c < NC; ++c) {
        const int buf = c & 1, nb = buf ^ 1;
        const bool has_next = (c + 1 < NC);
        if (has_next) {
            stage_B(c + 1, nb);
            if (!AFP32) stage_A_async(c + 1, nb);
            CP_COMMIT();
            if (AFP32) load_A_regs(c + 1);
        }

        const uint32_t abase = sb + buf * BUF + AOFF;
        const uint32_t bbase = sb + buf * BUF + b_tile;
        #pragma unroll
        for (int ks = 0; ks < 4; ++ks) {
            uint32_t af[2][4];
            #pragma unroll
            for (int m = 0; m < 2; ++m) {
                uint32_t off = SWZ((uint32_t)((warp_m * 32 + m * 16 + (lane & 15)) * 128
                                              + (((lane >> 4) << 3) + ks * 16) * 2));
                ldsm_x4(abase + off, af[m][0], af[m][1], af[m][2], af[m][3]);
            }
            #pragma unroll
            for (int p = 0; p < 4; ++p) {
                uint32_t off = SWZ((uint32_t)((b_row_base + p * 16) * 128
                                              + ks * 32 + b_colb));
                uint32_t b0, b1, b2, b3;
                ldsm_x4(bbase + off, b0, b1, b2, b3);
                #pragma unroll
                for (int m = 0; m < 2; ++m) {
                    mma_fp16(acc[m][p * 2 + 0], af[m], b0, b1);
                    mma_fp16(acc[m][p * 2 + 1], af[m], b2, b3);
                }
            }
        }

        if (has_next) {
            if (AFP32) convert_store_A(nb);
            CP_WAIT0();
        }
        __syncthreads();
    }

    // ---- epilogue (R10-proven) ----
    const bool is_z = warp_n >= 2;
    const int coln0 = (warp_n & 1) * 64;
    #pragma unroll
    for (int m = 0; m < 2; ++m) {
        int r0 = row0 + warp_m * 32 + m * 16 + (lane >> 2);
        int r1 = r0 + 8;
        #pragma unroll
        for (int f = 0; f < 8; ++f) {
            int col = coln0 + f * 8 + (lane & 3) * 2;
            if (is_z) {
                if (r0 < n)
                    *(__half2*)(Cz + (size_t)r0 * 128 + col) =
                        __floats2half2_rn(acc[m][f][0], acc[m][f][1]);
                if (r1 < n)
                    *(__half2*)(Cz + (size_t)r1 * 128 + col) =
                        __floats2half2_rn(acc[m][f][2], acc[m][f][3]);
            } else {
                if (r0 < n)
                    *(float2*)(Cs + (size_t)r0 * 128 + col) =
                        make_float2(acc[m][f][0], acc[m][f][1]);
                if (r1 < n)
                    *(float2*)(Cs + (size_t)r1 * 128 + col) =
                        make_float2(acc[m][f][2], acc[m][f][3]);
            }
        }
    }
}

// ---------------------------------------------------------------------------
// Quantize z: fp16 [n,128] -> BIASED uint8 [n,128] + per-row scale.
// Byte k of row = round(z_k/scale) + 128 (in [1,255]); scale = rowmax/127.
// Warp per row; lane owns features [4*lane, 4*lane+4).
// ---------------------------------------------------------------------------
__global__ __launch_bounds__(256) void quant_kernel(int n) {
    int w = (blockIdx.x * blockDim.x + threadIdx.x) >> 5;
    if (w >= n) return;
    int lane = threadIdx.x & 31;
    uint2 u = __ldg(&((const uint2*)g_z)[(size_t)w * 32 + lane]);
    float2 f0 = __half22float2(*(const __half2*)&u.x);
    float2 f1 = __half22float2(*(const __half2*)&u.y);
    float mx = fmaxf(fmaxf(fabsf(f0.x), fabsf(f0.y)),
                     fmaxf(fabsf(f1.x), fabsf(f1.y)));
    #pragma unroll
    for (int off = 16; off >= 1; off >>= 1)
        mx = fmaxf(mx, __shfl_xor_sync(0xffffffffu, mx, off));
    float inv = mx > 0.f ? 127.f / mx : 0.f;
    int q0 = (__float2int_rn(f0.x * inv) + 128) & 255;
    int q1 = (__float2int_rn(f0.y * inv) + 128) & 255;
    int q2 = (__float2int_rn(f1.x * inv) + 128) & 255;
    int q3 = (__float2int_rn(f1.y * inv) + 128) & 255;
    uint32_t packed = (uint32_t)q0 | ((uint32_t)q1 << 8)
                    | ((uint32_t)q2 << 16) | ((uint32_t)q3 << 24);
    ((uint32_t*)g_z8)[(size_t)w * 32 + lane] = packed;
    if (lane == 0) g_zsc[w] = mx > 0.f ? mx / 127.f : 0.f;
}

// ---------------------------------------------------------------------------
// Warp-level gather over ELL row, magic-float dequant:
//   byte t = q+128;  as_float(PRMT(u, 0x4B000000, 0x744k)) = 2^23 + t
//   value = s * ((fb - (2^23 + 128)))  — integer-exact, no I2F, no shifts.
// Lane owns features [4*lane, 4*lane+4) = one uint32 of the 128-byte row.
// ---------------------------------------------------------------------------
#define DEQ_EDGE(u, s)                                                          \
    do {                                                                        \
        float fb0 = __uint_as_float(__byte_perm((u), 0x4B000000u, 0x7440));     \
        float fb1 = __uint_as_float(__byte_perm((u), 0x4B000000u, 0x7441));     \
        float fb2 = __uint_as_float(__byte_perm((u), 0x4B000000u, 0x7442));     \
        float fb3 = __uint_as_float(__byte_perm((u), 0x4B000000u, 0x7443));     \
        a0 = fmaf((s), fb0 - 8388736.0f, a0);                                   \
        a1 = fmaf((s), fb1 - 8388736.0f, a1);                                   \
        a2 = fmaf((s), fb2 - 8388736.0f, a2);                                   \
        a3 = fmaf((s), fb3 - 8388736.0f, a3);                                   \
    } while (0)

__device__ __forceinline__ void gather_row_i8(const int* __restrict__ ell, int len,
                                              int lane,
                                              float& a0, float& a1,
                                              float& a2, float& a3) {
    const uint32_t* zp = (const uint32_t*)g_z8;
    int k = 0;
    for (; k + 3 < len; k += 4) {
        int4 j4 = __ldg((const int4*)(ell + k));       // 16B-aligned (k%4==0)
        uint32_t u0 = __ldg(&zp[(size_t)j4.x * 32 + lane]);
        uint32_t u1 = __ldg(&zp[(size_t)j4.y * 32 + lane]);
        uint32_t u2 = __ldg(&zp[(size_t)j4.z * 32 + lane]);
        uint32_t u3 = __ldg(&zp[(size_t)j4.w * 32 + lane]);
        float s0 = __ldg(&g_zsc[j4.x]);
        float s1 = __ldg(&g_zsc[j4.y]);
        float s2 = __ldg(&g_zsc[j4.z]);
        float s3 = __ldg(&g_zsc[j4.w]);
        DEQ_EDGE(u0, s0);
        DEQ_EDGE(u1, s1);
        DEQ_EDGE(u2, s2);
        DEQ_EDGE(u3, s3);
    }
    for (; k < len; ++k) {
        int j0 = __ldg(&ell[k]);
        uint32_t u0 = __ldg(&zp[(size_t)j0 * 32 + lane]);
        float s0 = __ldg(&g_zsc[j0]);
        DEQ_EDGE(u0, s0);
    }
}

// ---------------------------------------------------------------------------
// SpMM1: h1 = relu(s + gather/(deg+1)), written fp16 (GEMM2 A operand).
// ---------------------------------------------------------------------------
__global__ __launch_bounds__(256) void spmm1_kernel(
    const float* __restrict__ s, __half* __restrict__ h1, int n) {
    int w = (blockIdx.x * blockDim.x + threadIdx.x) >> 5;
    if (w >= n) return;
    int lane = threadIdx.x & 31;
    int deg = __ldg(&g_cnt[w]);
    int len = min(deg, ELLW);
    float a0 = 0.f, a1 = 0.f, a2 = 0.f, a3 = 0.f;
    gather_row_i8(g_ell + (size_t)w * ELLW, len, lane, a0, a1, a2, a3);
    float inv = 1.0f / (float)(deg + 1);
    float4 sv = __ldg(&((const float4*)s)[(size_t)w * 32 + lane]);
    float o0 = fmaxf(sv.x + a0 * inv, 0.f);
    float o1 = fmaxf(sv.y + a1 * inv, 0.f);
    float o2 = fmaxf(sv.z + a2 * inv, 0.f);
    float o3 = fmaxf(sv.w + a3 * inv, 0.f);
    __half2 p0 = __floats2half2_rn(o0, o1);
    __half2 p1 = __floats2half2_rn(o2, o3);
    ((uint2*)h1)[(size_t)w * 32 + lane] =
        make_uint2(*reinterpret_cast<uint32_t*>(&p0),
                   *reinterpret_cast<uint32_t*>(&p1));
}

// ---------------------------------------------------------------------------
// SpMM2 + MLP + log_softmax fused. Warp per node.
// ---------------------------------------------------------------------------
__global__ __launch_bounds__(256) void spmm2_mlp_kernel(
    const float* __restrict__ s,
    const float* __restrict__ W, const float* __restrict__ bias,
    float* __restrict__ out, int n) {
    __shared__ float Ws[NCLASS * 129];    // bank = (c + k) % 32, conflict-free
    __shared__ float rowbuf[8][136];
    const int tid = threadIdx.x;
    for (int i = tid; i < NCLASS * 128; i += 256) {
        int c = i >> 7, k = i & 127;
        Ws[c * 129 + k] = W[i];
    }
    __syncthreads();

    const int lane = tid & 31;
    const int wid  = tid >> 5;
    int w = blockIdx.x * 8 + wid;
    if (w >= n) return;

    int deg = __ldg(&g_cnt[w]);
    int len = min(deg, ELLW);
    float a0 = 0.f, a1 = 0.f, a2 = 0.f, a3 = 0.f;
    gather_row_i8(g_ell + (size_t)w * ELLW, len, lane, a0, a1, a2, a3);
    float inv = 1.0f / (float)(deg + 1);
    float4 sv = __ldg(&((const float4*)s)[(size_t)w * 32 + lane]);
    float o0 = fmaxf(sv.x + a0 * inv, 0.f);
    float o1 = fmaxf(sv.y + a1 * inv, 0.f);
    float o2 = fmaxf(sv.z + a2 * inv, 0.f);
    float o3 = fmaxf(sv.w + a3 * inv, 0.f);

    *(float4*)&rowbuf[wid][lane * 4] = make_float4(o0, o1, o2, o3);
    __syncwarp();

    float v0 = __ldg(&bias[lane]);
    float v1 = (lane < NCLASS - 32) ? __ldg(&bias[lane + 32]) : 0.f;
    const float* hr = rowbuf[wid];
    #pragma unroll 8
    for (int k = 0; k < 128; ++k) {
        float hh = hr[k];
        v0 = fmaf(hh, Ws[lane * 129 + k], v0);
        if (lane < 8) v1 = fmaf(hh, Ws[(lane + 32) * 129 + k], v1);
    }
    float m = v0;
    if (lane < 8) m = fmaxf(m, v1);
    #pragma unroll
    for (int off = 16; off >= 1; off >>= 1)
        m = fmaxf(m, __shfl_xor_sync(0xffffffffu, m, off));
    float sum = expf(v0 - m) + ((lane < 8) ? expf(v1 - m) : 0.f);
    #pragma unroll
    for (int off = 16; off >= 1; off >>= 1)
        sum += __shfl_xor_sync(0xffffffffu, sum, off);
    float ls = logf(sum);
    float* orow = out + (size_t)w * NCLASS;
    orow[lane] = v0 - m - ls;
    if (lane < 8) orow[32 + lane] = v1 - m - ls;
}

// ---------------------------------------------------------------------------
// Launch
// ---------------------------------------------------------------------------
extern "C" void kernel_launch(void* const* d_in, const int* in_sizes, int n_in,
                              void* d_out, int out_size) {
    const float* x    = (const float*)d_in[0];
    const float* W1   = (const float*)d_in[1];
    const float* W2   = (const float*)d_in[2];
    const float* mlpW = (const float*)d_in[3];
    const float* mlpb = (const float*)d_in[4];
    const int*   rows = (const int*)d_in[5];
    const int*   cols = (const int*)d_in[6];
    const int n = in_sizes[0] / NFEAT;
    const int e = in_sizes[5];
    float* out = (float*)d_out;

    void *p_s, *p_z, *p_h1, *p_w1s, *p_w1n, *p_w2s, *p_w2n;
    cudaGetSymbolAddress(&p_s, g_s);
    cudaGetSymbolAddress(&p_z, g_z);
    cudaGetSymbolAddress(&p_h1, g_h1);
    cudaGetSymbolAddress(&p_w1s, g_w1s);
    cudaGetSymbolAddress(&p_w1n, g_w1n);
    cudaGetSymbolAddress(&p_w2s, g_w2s);
    cudaGetSymbolAddress(&p_w2n, g_w2n);

    constexpr int SMEM = 2 * 49152;   // 96 KB double buffer
    cudaFuncSetAttribute((const void*)mma_gemm_kernel<256, true, true>,
                         cudaFuncAttributeMaxDynamicSharedMemorySize, SMEM);
    cudaFuncSetAttribute((const void*)mma_gemm_kernel<128, false, false>,
                         cudaFuncAttributeMaxDynamicSharedMemorySize, SMEM);

    int nsm = 148;
    cudaDeviceGetAttribute(&nsm, cudaDevAttrMultiProcessorCount, 0);

    // Prep: fp16 weight slices + degree-counter zero
    prep_kernel<<<(n + 255) / 256, 256>>>(W1, W2, n);

    const int gx = (n + 127) / 128;
    int fillb = (nsm - (gx % nsm)) + nsm;   // tail slots + one full wave
    const int spmm_blocks = (n * 32 + 255) / 256;

    // Layer 1 GEMM (+ELL build in tail blocks): s fp32, z fp16
    mma_gemm_kernel<256, true, true><<<gx + fillb, 512, SMEM>>>(
        x, nullptr, (const __half*)p_w1s, (const __half*)p_w1n,
        (float*)p_s, (__half*)p_z, n, gx, rows, cols, e);
    // Quantize z -> biased int8 + per-row scale
    quant_kernel<<<spmm_blocks, 256>>>(n);
    spmm1_kernel<<<spmm_blocks, 256>>>(
        (const float*)p_s, (__half*)p_h1, n);

    // Layer 2: A = h1 fp16 (pure cp.async path)
    mma_gemm_kernel<128, false, false><<<gx, 512, SMEM>>>(
        nullptr, (const __half*)p_h1, (const __half*)p_w2s, (const __half*)p_w2n,
        (float*)p_s, (__half*)p_z, n, gx, nullptr, nullptr, 0);
    quant_kernel<<<spmm_blocks, 256>>>(n);

    // SpMM2 + MLP + log_softmax fused
    spmm2_mlp_kernel<<<(n + 7) / 8, 256>>>(
        (const float*)p_s, mlpW, mlpb, out, n);
}

// round 16
// speedup vs baseline: 1.1614x; 1.1614x over previous
#include <cuda_runtime.h>
#include <cuda_bf16.h>
#include <cuda_fp16.h>
#include <math.h>
#include <stdint.h>

// Problem constants
#define NFEAT   256
#define NHID    128
#define NCLASS  40
#define MAXN    100000
#define MAXE    3200000
#define ELLW    96            // ELL width: P(Poisson(32) > 96) ~ 1e-20
#define NPAD    (MAXN + 128)  // rows padded so cp.async tail reads stay in-bounds

// ---------------------------------------------------------------------------
// Static device scratch
// ---------------------------------------------------------------------------
__device__ int    g_cnt[MAXN];                     // degree (atomic slot counter)
__device__ int    g_ell[(size_t)MAXN * ELLW];      // ELL adjacency (38.4 MB)
__device__ float  g_s[(size_t)MAXN * NHID];        // self-projection (fp32)
__device__ __half g_z[(size_t)MAXN * NHID];        // neigh-projection (fp16)
__device__ uint8_t g_z8[(size_t)MAXN * NHID];      // quantized z, BIASED bytes (q+128)
__device__ float  g_zmax[2];                       // global |z| max per layer
__device__ __half g_h1[(size_t)NPAD * NHID];       // h1 (fp16, GEMM2 A operand)
// fp16 weights, [128 out-rows, K in-cols] K-major (= torch native slices)
__device__ __half g_w1s[128 * 256], g_w1n[128 * 256];
__device__ __half g_w2s[128 * 128], g_w2n[128 * 128];

// ---------------------------------------------------------------------------
// Helpers
// ---------------------------------------------------------------------------
__device__ __forceinline__ uint32_t smem_u32(const void* p) {
    uint32_t a;
    asm("{ .reg .u64 t; cvta.to.shared.u64 t, %1; cvt.u32.u64 %0, t; }"
        : "=r"(a) : "l"(p));
    return a;
}

#define SWZ(x) ((x) ^ (((x) >> 3) & 0x70))

__device__ __forceinline__ void ldsm_x4(uint32_t addr, uint32_t& r0, uint32_t& r1,
                                        uint32_t& r2, uint32_t& r3) {
    asm volatile("ldmatrix.sync.aligned.m8n8.x4.shared.b16 {%0,%1,%2,%3}, [%4];"
                 : "=r"(r0), "=r"(r1), "=r"(r2), "=r"(r3) : "r"(addr));
}

__device__ __forceinline__ void mma_fp16(float* d, const uint32_t* a,
                                         uint32_t b0, uint32_t b1) {
    asm volatile(
        "mma.sync.aligned.m16n8k16.row.col.f32.f16.f16.f32 "
        "{%0,%1,%2,%3}, {%4,%5,%6,%7}, {%8,%9}, {%0,%1,%2,%3};"
        : "+f"(d[0]), "+f"(d[1]), "+f"(d[2]), "+f"(d[3])
        : "r"(a[0]), "r"(a[1]), "r"(a[2]), "r"(a[3]), "r"(b0), "r"(b1));
}

__device__ __forceinline__ void cp16(uint32_t dst, const void* src) {
    asm volatile("cp.async.cg.shared.global [%0], [%1], 16;"
                 :: "r"(dst), "l"(src));
}
#define CP_COMMIT() asm volatile("cp.async.commit_group;" ::: "memory")
#define CP_WAIT0()  asm volatile("cp.async.wait_group 0;" ::: "memory")

// ---------------------------------------------------------------------------
// Merged prep: W1 -> fp16 slices, W2, zero g_cnt, zero g_zmax
// ---------------------------------------------------------------------------
__global__ void prep_kernel(const float* __restrict__ W1,
                            const float* __restrict__ W2, int n) {
    int idx = blockIdx.x * blockDim.x + threadIdx.x;
    if (idx < 128 * 256) {
        int j = idx >> 8, k = idx & 255;
        g_w1s[idx] = __float2half_rn(W1[j * 512 + k]);
        g_w1n[idx] = __float2half_rn(W1[j * 512 + 256 + k]);
    }
    if (idx < 128 * 128) {
        int j = idx >> 7, k = idx & 127;
        g_w2s[idx] = __float2half_rn(W2[j * 256 + k]);
        g_w2n[idx] = __float2half_rn(W2[j * 256 + 128 + k]);
    }
    if (idx < n) g_cnt[idx] = 0;
    if (idx < 2) g_zmax[idx] = 0.f;
}

// ---------------------------------------------------------------------------
// Merged double-buffered fp16 GEMM (mma.sync m16n8k16) — R10-proven epilogue
// plus a z-warp max|acc| reduction into g_zmax[zslot]:
//   s[blk,128] = A @ Bs^T (fp32 out),  z[blk,128] = A @ Bn^T (fp16 out)
// Block 128 rows x 256 out-cols, 512 threads = 16 warps (4 M x 4 N of 32x64).
// AFP32: A fp32 in gmem, converted to fp16 in smem (register-prefetched).
// EFILL: blocks with blockIdx.x >= gemm_blocks build the ELL adjacency.
// ---------------------------------------------------------------------------
template <int K, bool AFP32, bool EFILL>
__global__ __launch_bounds__(512, 1) void mma_gemm_kernel(
    const float* __restrict__ A,
    const __half* __restrict__ Ah,
    const __half* __restrict__ Bs, const __half* __restrict__ Bn,
    float* __restrict__ Cs, __half* __restrict__ Cz, int n, int zslot,
    int gemm_blocks, const int* __restrict__ rows,
    const int* __restrict__ cols, int e) {
    // ---- ELL-fill role (tail blocks) ----
    if (EFILL && (int)blockIdx.x >= gemm_blocks) {
        const int fb  = blockIdx.x - gemm_blocks;
        const int nfb = gridDim.x - gemm_blocks;
        const int tid = threadIdx.x;
        const int total4 = e >> 2;
        const int4* r4p = (const int4*)rows;
        const int4* c4p = (const int4*)cols;
        for (int i = fb * 512 + tid; i < total4; i += nfb * 512) {
            int4 r = __ldg(&r4p[i]);
            int4 c = __ldg(&c4p[i]);
            int p;
            p = atomicAdd(&g_cnt[r.x], 1); if (p < ELLW) g_ell[(size_t)r.x * ELLW + p] = c.x;
            p = atomicAdd(&g_cnt[r.y], 1); if (p < ELLW) g_ell[(size_t)r.y * ELLW + p] = c.y;
            p = atomicAdd(&g_cnt[r.z], 1); if (p < ELLW) g_ell[(size_t)r.z * ELLW + p] = c.z;
            p = atomicAdd(&g_cnt[r.w], 1); if (p < ELLW) g_ell[(size_t)r.w * ELLW + p] = c.w;
        }
        if (fb == 0) {       // scalar tail (e % 4)
            for (int i = (total4 << 2) + tid; i < e; i += 512) {
                int r = __ldg(&rows[i]), c = __ldg(&cols[i]);
                int p = atomicAdd(&g_cnt[r], 1);
                if (p < ELLW) g_ell[(size_t)r * ELLW + p] = c;
            }
        }
        return;
    }

    extern __shared__ char smem[];
    constexpr int BUF  = 49152;          // A 16K + Bs 16K + Bn 16K
    constexpr int AOFF = 0;
    constexpr int BOFF = 16384;
    constexpr int NC   = K / 64;
    const uint32_t sb = smem_u32(smem);
    const int tid    = threadIdx.x;
    const int lane   = tid & 31;
    const int wid    = tid >> 5;
    const int warp_m = wid & 3;
    const int warp_n = wid >> 2;
    const int row0   = blockIdx.x * 128;

    float acc[2][8][4];
    #pragma unroll
    for (int m = 0; m < 2; ++m)
        #pragma unroll
        for (int f = 0; f < 8; ++f)
            #pragma unroll
            for (int q = 0; q < 4; ++q) acc[m][f][q] = 0.f;

    auto stage_B = [&](int c, int buf) {
        #pragma unroll
        for (int t = 0; t < 2; ++t) {
            const __half* B = t ? Bn : Bs;
            #pragma unroll
            for (int i = tid; i < 1024; i += 512) {
                int row = i >> 3, j = i & 7;
                cp16(sb + buf * BUF + BOFF + t * 16384 + SWZ((uint32_t)(row * 128 + j * 16)),
                     B + (size_t)row * K + c * 64 + j * 8);
            }
        }
    };
    auto stage_A_async = [&](int c, int buf) {
        #pragma unroll
        for (int i = tid; i < 1024; i += 512) {
            int row = i >> 3, j = i & 7;
            cp16(sb + buf * BUF + AOFF + SWZ((uint32_t)(row * 128 + j * 16)),
                 Ah + (size_t)(row0 + row) * K + c * 64 + j * 8);
        }
    };
    float ar[2][8];
    auto load_A_regs = [&](int c) {
        #pragma unroll
        for (int t = 0; t < 2; ++t) {
            int g = tid + t * 512;
            int row = g >> 3, j = g & 7;
            int grow = row0 + row;
            float4 f0 = make_float4(0.f, 0.f, 0.f, 0.f), f1 = f0;
            if (grow < n) {
                const float* ap = A + (size_t)grow * K + c * 64 + j * 8;
                f0 = *(const float4*)ap;
                f1 = *(const float4*)(ap + 4);
            }
            ar[t][0] = f0.x; ar[t][1] = f0.y; ar[t][2] = f0.z; ar[t][3] = f0.w;
            ar[t][4] = f1.x; ar[t][5] = f1.y; ar[t][6] = f1.z; ar[t][7] = f1.w;
        }
    };
    auto convert_store_A = [&](int buf) {
        #pragma unroll
        for (int t = 0; t < 2; ++t) {
            int g = tid + t * 512;
            int row = g >> 3, j = g & 7;
            uint32_t hv[4];
            #pragma unroll
            for (int q = 0; q < 4; ++q) {
                __half2 hp = __floats2half2_rn(ar[t][2 * q], ar[t][2 * q + 1]);
                hv[q] = *reinterpret_cast<uint32_t*>(&hp);
            }
            *(uint4*)(smem + buf * BUF + AOFF + SWZ((uint32_t)(row * 128 + j * 16))) =
                make_uint4(hv[0], hv[1], hv[2], hv[3]);
        }
    };

    const uint32_t b_tile = BOFF + (warp_n >> 1) * 16384;   // Bs or Bn tile
    const int b_row_base = (warp_n & 1) * 64 + ((lane >> 4) << 3) + (lane & 7);
    const uint32_t b_colb = ((lane >> 3) & 1) * 16;

    stage_B(0, 0);
    if (!AFP32) {
        stage_A_async(0, 0);
        CP_COMMIT();
    } else {
        CP_COMMIT();
        load_A_regs(0);
        convert_store_A(0);
    }
    CP_WAIT0();
    __syncthreads();

    for (int c = 0; c < NC; ++c) {
        const int buf = c & 1, nb = buf ^ 1;
        const bool has_next = (c + 1 < NC);
        if (has_next) {
            stage_B(c + 1, nb);
            if (!AFP32) stage_A_async(c + 1, nb);
            CP_COMMIT();
            if (AFP32) load_A_regs(c + 1);
        }

        const uint32_t abase = sb + buf * BUF + AOFF;
        const uint32_t bbase = sb + buf * BUF + b_tile;
        #pragma unroll
        for (int ks = 0; ks < 4; ++ks) {
            uint32_t af[2][4];
            #pragma unroll
            for (int m = 0; m < 2; ++m) {
                uint32_t off = SWZ((uint32_t)((warp_m * 32 + m * 16 + (lane & 15)) * 128
                                              + (((lane >> 4) << 3) + ks * 16) * 2));
                ldsm_x4(abase + off, af[m][0], af[m][1], af[m][2], af[m][3]);
            }
            #pragma unroll
            for (int p = 0; p < 4; ++p) {
                uint32_t off = SWZ((uint32_t)((b_row_base + p * 16) * 128
                                              + ks * 32 + b_colb));
                uint32_t b0, b1, b2, b3;
                ldsm_x4(bbase + off, b0, b1, b2, b3);
                #pragma unroll
                for (int m = 0; m < 2; ++m) {
                    mma_fp16(acc[m][p * 2 + 0], af[m], b0, b1);
                    mma_fp16(acc[m][p * 2 + 1], af[m], b2, b3);
                }
            }
        }

        if (has_next) {
            if (AFP32) convert_store_A(nb);
            CP_WAIT0();
        }
        __syncthreads();
    }

    // ---- epilogue (R10-proven) + z-warp global max reduction ----
    const bool is_z = warp_n >= 2;
    const int coln0 = (warp_n & 1) * 64;
    #pragma unroll
    for (int m = 0; m < 2; ++m) {
        int r0 = row0 + warp_m * 32 + m * 16 + (lane >> 2);
        int r1 = r0 + 8;
        #pragma unroll
        for (int f = 0; f < 8; ++f) {
            int col = coln0 + f * 8 + (lane & 3) * 2;
            if (is_z) {
                if (r0 < n)
                    *(__half2*)(Cz + (size_t)r0 * 128 + col) =
                        __floats2half2_rn(acc[m][f][0], acc[m][f][1]);
                if (r1 < n)
                    *(__half2*)(Cz + (size_t)r1 * 128 + col) =
                        __floats2half2_rn(acc[m][f][2], acc[m][f][3]);
            } else {
                if (r0 < n)
                    *(float2*)(Cs + (size_t)r0 * 128 + col) =
                        make_float2(acc[m][f][0], acc[m][f][1]);
                if (r1 < n)
                    *(float2*)(Cs + (size_t)r1 * 128 + col) =
                        make_float2(acc[m][f][2], acc[m][f][3]);
            }
        }
    }
    if (is_z) {
        float mx = 0.f;
        #pragma unroll
        for (int m = 0; m < 2; ++m)
            #pragma unroll
            for (int f = 0; f < 8; ++f)
                #pragma unroll
                for (int q = 0; q < 4; ++q)
                    mx = fmaxf(mx, fabsf(acc[m][f][q]));
        #pragma unroll
        for (int off = 16; off >= 1; off >>= 1)
            mx = fmaxf(mx, __shfl_xor_sync(0xffffffffu, mx, off));
        if (lane == 0)
            atomicMax((int*)&g_zmax[zslot], __float_as_int(mx));  // mx >= 0
    }
}

// ---------------------------------------------------------------------------
// Quantize z: fp16 [n,128] -> BIASED uint8 [n,128], GLOBAL scale g_zmax[slot].
// Byte k of row = clamp(round(z_k*127/zmax), -127, 127) + 128.
// Warp per row; lane owns features [4*lane, 4*lane+4).
// ---------------------------------------------------------------------------
__global__ __launch_bounds__(256) void quant_kernel(int n, int slot) {
    int w = (blockIdx.x * blockDim.x + threadIdx.x) >> 5;
    if (w >= n) return;
    int lane = threadIdx.x & 31;
    float zm = g_zmax[slot];
    float inv = zm > 0.f ? 127.f / zm : 0.f;
    uint2 u = __ldg(&((const uint2*)g_z)[(size_t)w * 32 + lane]);
    float2 f0 = __half22float2(*(const __half2*)&u.x);
    float2 f1 = __half22float2(*(const __half2*)&u.y);
    int q0 = min(127, max(-127, __float2int_rn(f0.x * inv))) + 128;
    int q1 = min(127, max(-127, __float2int_rn(f0.y * inv))) + 128;
    int q2 = min(127, max(-127, __float2int_rn(f1.x * inv))) + 128;
    int q3 = min(127, max(-127, __float2int_rn(f1.y * inv))) + 128;
    uint32_t packed = (uint32_t)q0 | ((uint32_t)q1 << 8)
                    | ((uint32_t)q2 << 16) | ((uint32_t)q3 << 24);
    ((uint32_t*)g_z8)[(size_t)w * 32 + lane] = packed;
}

// ---------------------------------------------------------------------------
// Warp-level gather over ELL row — PURE INTEGER accumulation:
//   ae += u & 0x00FF00FF (features 0,2); ao += (u>>8) & 0x00FF00FF (1,3).
//   16-bit fields; max 96*255 = 24480 < 2^15, no cross-field carry.
// Dequant once per row: a_k = Sg * (sum_k - 128*len)  (exact).
// ---------------------------------------------------------------------------
__device__ __forceinline__ void gather_row_int(const int* __restrict__ ell, int len,
                                               int lane,
                                               uint32_t& ae, uint32_t& ao) {
    const uint32_t* zp = (const uint32_t*)g_z8;
    int k = 0;
    for (; k + 3 < len; k += 4) {
        int4 j4 = __ldg((const int4*)(ell + k));       // 16B-aligned (k%4==0)
        uint32_t u0 = __ldg(&zp[(size_t)j4.x * 32 + lane]);
        uint32_t u1 = __ldg(&zp[(size_t)j4.y * 32 + lane]);
        uint32_t u2 = __ldg(&zp[(size_t)j4.z * 32 + lane]);
        uint32_t u3 = __ldg(&zp[(size_t)j4.w * 32 + lane]);
        ae += u0 & 0x00FF00FFu;  ao += (u0 >> 8) & 0x00FF00FFu;
        ae += u1 & 0x00FF00FFu;  ao += (u1 >> 8) & 0x00FF00FFu;
        ae += u2 & 0x00FF00FFu;  ao += (u2 >> 8) & 0x00FF00FFu;
        ae += u3 & 0x00FF00FFu;  ao += (u3 >> 8) & 0x00FF00FFu;
    }
    for (; k < len; ++k) {
        int j0 = __ldg(&ell[k]);
        uint32_t u0 = __ldg(&zp[(size_t)j0 * 32 + lane]);
        ae += u0 & 0x00FF00FFu;  ao += (u0 >> 8) & 0x00FF00FFu;
    }
}

// ---------------------------------------------------------------------------
// SpMM1: h1 = relu(s + gather/(deg+1)), written fp16 (GEMM2 A operand).
// ---------------------------------------------------------------------------
__global__ __launch_bounds__(256) void spmm1_kernel(
    const float* __restrict__ s, __half* __restrict__ h1, int n, int slot) {
    int w = (blockIdx.x * blockDim.x + threadIdx.x) >> 5;
    if (w >= n) return;
    int lane = threadIdx.x & 31;
    int deg = __ldg(&g_cnt[w]);
    int len = min(deg, ELLW);
    uint32_t ae = 0, ao = 0;
    gather_row_int(g_ell + (size_t)w * ELLW, len, lane, ae, ao);
    float Sg = g_zmax[slot] * (1.0f / 127.0f);
    float bias = 128.0f * (float)len;
    float a0 = ((float)(ae & 0xFFFFu) - bias) * Sg;
    float a2 = ((float)(ae >> 16)    - bias) * Sg;
    float a1 = ((float)(ao & 0xFFFFu) - bias) * Sg;
    float a3 = ((float)(ao >> 16)    - bias) * Sg;
    float inv = 1.0f / (float)(deg + 1);
    float4 sv = __ldg(&((const float4*)s)[(size_t)w * 32 + lane]);
    float o0 = fmaxf(sv.x + a0 * inv, 0.f);
    float o1 = fmaxf(sv.y + a1 * inv, 0.f);
    float o2 = fmaxf(sv.z + a2 * inv, 0.f);
    float o3 = fmaxf(sv.w + a3 * inv, 0.f);
    __half2 p0 = __floats2half2_rn(o0, o1);
    __half2 p1 = __floats2half2_rn(o2, o3);
    ((uint2*)h1)[(size_t)w * 32 + lane] =
        make_uint2(*reinterpret_cast<uint32_t*>(&p0),
                   *reinterpret_cast<uint32_t*>(&p1));
}

// ---------------------------------------------------------------------------
// SpMM2 + MLP + log_softmax fused. Warp per node.
// ---------------------------------------------------------------------------
__global__ __launch_bounds__(256) void spmm2_mlp_kernel(
    const float* __restrict__ s,
    const float* __restrict__ W, const float* __restrict__ bias,
    float* __restrict__ out, int n, int slot) {
    __shared__ float Ws[NCLASS * 129];    // bank = (c + k) % 32, conflict-free
    __shared__ float rowbuf[8][136];
    const int tid = threadIdx.x;
    for (int i = tid; i < NCLASS * 128; i += 256) {
        int c = i >> 7, k = i & 127;
        Ws[c * 129 + k] = W[i];
    }
    __syncthreads();

    const int lane = tid & 31;
    const int wid  = tid >> 5;
    int w = blockIdx.x * 8 + wid;
    if (w >= n) return;

    int deg = __ldg(&g_cnt[w]);
    int len = min(deg, ELLW);
    uint32_t ae = 0, ao = 0;
    gather_row_int(g_ell + (size_t)w * ELLW, len, lane, ae, ao);
    float Sg = g_zmax[slot] * (1.0f / 127.0f);
    float qb = 128.0f * (float)len;
    float a0 = ((float)(ae & 0xFFFFu) - qb) * Sg;
    float a2 = ((float)(ae >> 16)    - qb) * Sg;
    float a1 = ((float)(ao & 0xFFFFu) - qb) * Sg;
    float a3 = ((float)(ao >> 16)    - qb) * Sg;
    float inv = 1.0f / (float)(deg + 1);
    float4 sv = __ldg(&((const float4*)s)[(size_t)w * 32 + lane]);
    float o0 = fmaxf(sv.x + a0 * inv, 0.f);
    float o1 = fmaxf(sv.y + a1 * inv, 0.f);
    float o2 = fmaxf(sv.z + a2 * inv, 0.f);
    float o3 = fmaxf(sv.w + a3 * inv, 0.f);

    *(float4*)&rowbuf[wid][lane * 4] = make_float4(o0, o1, o2, o3);
    __syncwarp();

    float v0 = __ldg(&bias[lane]);
    float v1 = (lane < NCLASS - 32) ? __ldg(&bias[lane + 32]) : 0.f;
    const float* hr = rowbuf[wid];
    #pragma unroll 8
    for (int k = 0; k < 128; ++k) {
        float hh = hr[k];
        v0 = fmaf(hh, Ws[lane * 129 + k], v0);
        if (lane < 8) v1 = fmaf(hh, Ws[(lane + 32) * 129 + k], v1);
    }
    float m = v0;
    if (lane < 8) m = fmaxf(m, v1);
    #pragma unroll
    for (int off = 16; off >= 1; off >>= 1)
        m = fmaxf(m, __shfl_xor_sync(0xffffffffu, m, off));
    float sum = expf(v0 - m) + ((lane < 8) ? expf(v1 - m) : 0.f);
    #pragma unroll
    for (int off = 16; off >= 1; off >>= 1)
        sum += __shfl_xor_sync(0xffffffffu, sum, off);
    float ls = logf(sum);
    float* orow = out + (size_t)w * NCLASS;
    orow[lane] = v0 - m - ls;
    if (lane < 8) orow[32 + lane] = v1 - m - ls;
}

// ---------------------------------------------------------------------------
// Launch
// ---------------------------------------------------------------------------
extern "C" void kernel_launch(void* const* d_in, const int* in_sizes, int n_in,
                              void* d_out, int out_size) {
    const float* x    = (const float*)d_in[0];
    const float* W1   = (const float*)d_in[1];
    const float* W2   = (const float*)d_in[2];
    const float* mlpW = (const float*)d_in[3];
    const float* mlpb = (const float*)d_in[4];
    const int*   rows = (const int*)d_in[5];
    const int*   cols = (const int*)d_in[6];
    const int n = in_sizes[0] / NFEAT;
    const int e = in_sizes[5];
    float* out = (float*)d_out;

    void *p_s, *p_z, *p_h1, *p_w1s, *p_w1n, *p_w2s, *p_w2n;
    cudaGetSymbolAddress(&p_s, g_s);
    cudaGetSymbolAddress(&p_z, g_z);
    cudaGetSymbolAddress(&p_h1, g_h1);
    cudaGetSymbolAddress(&p_w1s, g_w1s);
    cudaGetSymbolAddress(&p_w1n, g_w1n);
    cudaGetSymbolAddress(&p_w2s, g_w2s);
    cudaGetSymbolAddress(&p_w2n, g_w2n);

    constexpr int SMEM = 2 * 49152;   // 96 KB double buffer
    cudaFuncSetAttribute((const void*)mma_gemm_kernel<256, true, true>,
                         cudaFuncAttributeMaxDynamicSharedMemorySize, SMEM);
    cudaFuncSetAttribute((const void*)mma_gemm_kernel<128, false, false>,
                         cudaFuncAttributeMaxDynamicSharedMemorySize, SMEM);

    int nsm = 148;
    cudaDeviceGetAttribute(&nsm, cudaDevAttrMultiProcessorCount, 0);

    // Prep: fp16 weight slices + degree-counter zero + zmax zero
    prep_kernel<<<(n + 255) / 256, 256>>>(W1, W2, n);

    const int gx = (n + 127) / 128;
    int fillb = (nsm - (gx % nsm)) + nsm;   // tail slots + one full wave
    const int spmm_blocks = (n * 32 + 255) / 256;

    // Layer 1 GEMM (+ELL build in tail blocks): s fp32, z fp16 + zmax[0]
    mma_gemm_kernel<256, true, true><<<gx + fillb, 512, SMEM>>>(
        x, nullptr, (const __half*)p_w1s, (const __half*)p_w1n,
        (float*)p_s, (__half*)p_z, n, 0, gx, rows, cols, e);
    // Quantize z -> biased int8 (global scale)
    quant_kernel<<<spmm_blocks, 256>>>(n, 0);
    spmm1_kernel<<<spmm_blocks, 256>>>(
        (const float*)p_s, (__half*)p_h1, n, 0);

    // Layer 2: A = h1 fp16 (pure cp.async path) + zmax[1]
    mma_gemm_kernel<128, false, false><<<gx, 512, SMEM>>>(
        nullptr, (const __half*)p_h1, (const __half*)p_w2s, (const __half*)p_w2n,
        (float*)p_s, (__half*)p_z, n, 1, gx, nullptr, nullptr, 0);
    quant_kernel<<<spmm_blocks, 256>>>(n, 1);

    // SpMM2 + MLP + log_softmax fused
    spmm2_mlp_kernel<<<(n + 7) / 8, 256>>>(
        (const float*)p_s, mlpW, mlpb, out, n, 1);
}